// round 3
// baseline (speedup 1.0000x reference)
#include <cuda_runtime.h>

#define NN 200000
#define NE 6400000
#define AF 82
#define HID 10
#define ED 6
#define PSTR 12          // padded row stride for P (floats)
#define NB1 196          // ceil(NN / 1024) scan blocks

// ---- persistent scratch (static device globals; allocation-free) -----------
__device__ __align__(16) float g_h[NN * HID];           // current hidden
__device__ __align__(16) float g_P[2][NN * PSTR];       // double-buffered P = h @ Wg[0:10]
__device__ __align__(16) float g_edges[(size_t)NE * 8]; // binned records: {src, ef[6], pad} 32B
__device__ int g_deg[NN];
__device__ int g_off[NN + 1];
__device__ int g_pos[NN];
__device__ int g_bsum[NB1];

__device__ __forceinline__ float lrelu(float x) { return x > 0.f ? x : 0.1f * x; }

// ---------------------------------------------------------------------------
// h = lrelu(vertex @ Wi);  P[0] = h @ Wg[0:10]
// ---------------------------------------------------------------------------
__global__ void __launch_bounds__(128) init_kernel(const float* __restrict__ vertex,
                                                   const float* __restrict__ Wi,
                                                   const float* __restrict__ Wg)
{
    __shared__ float sv[128 * AF];
    __shared__ float sWi[AF * HID];
    __shared__ float sWgh[HID * HID];
    const int tid = threadIdx.x;
    const int base = blockIdx.x * 128;

    for (int i = tid; i < AF * HID; i += 128) sWi[i] = Wi[i];
    for (int i = tid; i < HID * HID; i += 128) sWgh[i] = Wg[i];

    const int nrows = min(128, NN - base);
    const int total = nrows * AF;
    const float* vsrc = vertex + (size_t)base * AF;
    for (int i = tid; i < total; i += 128) sv[i] = vsrc[i];
    __syncthreads();

    if (tid < nrows) {
        const int node = base + tid;
        float acc[HID];
#pragma unroll
        for (int j = 0; j < HID; j++) acc[j] = 0.f;
        const float* row = &sv[tid * AF];
#pragma unroll 2
        for (int k = 0; k < AF; k++) {
            const float v = row[k];
#pragma unroll
            for (int j = 0; j < HID; j++) acc[j] += v * sWi[k * HID + j];
        }
        float h[HID];
#pragma unroll
        for (int j = 0; j < HID; j++) {
            h[j] = lrelu(acc[j]);
            g_h[(size_t)node * HID + j] = h[j];
        }
        float p[HID];
#pragma unroll
        for (int j = 0; j < HID; j++) p[j] = 0.f;
#pragma unroll
        for (int k = 0; k < HID; k++) {
#pragma unroll
            for (int j = 0; j < HID; j++) p[j] += h[k] * sWgh[k * HID + j];
        }
#pragma unroll
        for (int j = 0; j < HID; j++) g_P[0][(size_t)node * PSTR + j] = p[j];
    }
}

// ---------------------------------------------------------------------------
// CSR build: zero degrees, histogram, 3-stage scan, permute edges
// ---------------------------------------------------------------------------
__global__ void zero_deg_kernel() {
    const int i = blockIdx.x * blockDim.x + threadIdx.x;
    if (i < NN) g_deg[i] = 0;
}

__global__ void __launch_bounds__(256) hist_kernel(const int* __restrict__ dst) {
    const int e = blockIdx.x * blockDim.x + threadIdx.x;
    if (e < NE) atomicAdd(&g_deg[dst[e]], 1);
}

// smem exclusive scan over 256 values; leaves inclusive total in s[255]
__device__ __forceinline__ int block_excl_scan(int val, int* s) {
    const int tid = threadIdx.x;
    s[tid] = val;
    __syncthreads();
#pragma unroll
    for (int off = 1; off < 256; off <<= 1) {
        int v = (tid >= off) ? s[tid - off] : 0;
        __syncthreads();
        s[tid] += v;
        __syncthreads();
    }
    return s[tid] - val;
}

__global__ void __launch_bounds__(256) scan1_kernel() {
    __shared__ int s[256];
    const int tid = threadIdx.x;
    const int base = blockIdx.x * 1024 + tid * 4;
    int sum = 0;
#pragma unroll
    for (int j = 0; j < 4; j++) {
        const int idx = base + j;
        if (idx < NN) sum += g_deg[idx];
    }
    (void)block_excl_scan(sum, s);
    if (tid == 255) g_bsum[blockIdx.x] = s[255];
}

__global__ void __launch_bounds__(256) scan2_kernel() {
    __shared__ int s[256];
    const int tid = threadIdx.x;
    int v = (tid < NB1) ? g_bsum[tid] : 0;
    int ex = block_excl_scan(v, s);
    if (tid < NB1) g_bsum[tid] = ex;
    if (tid == 0) g_off[NN] = NE;
}

__global__ void __launch_bounds__(256) scan3_kernel() {
    __shared__ int s[256];
    const int tid = threadIdx.x;
    const int base = blockIdx.x * 1024 + tid * 4;
    int d[4];
    int sum = 0;
#pragma unroll
    for (int j = 0; j < 4; j++) {
        const int idx = base + j;
        d[j] = (idx < NN) ? g_deg[idx] : 0;
        sum += d[j];
    }
    int run = block_excl_scan(sum, s) + g_bsum[blockIdx.x];
#pragma unroll
    for (int j = 0; j < 4; j++) {
        const int idx = base + j;
        if (idx < NN) { g_off[idx] = run; g_pos[idx] = run; }
        run += d[j];
    }
}

__global__ void __launch_bounds__(256) permute_kernel(const float* __restrict__ ef,
                                                      const int* __restrict__ src,
                                                      const int* __restrict__ dst)
{
    const int e = blockIdx.x * blockDim.x + threadIdx.x;
    if (e >= NE) return;
    const int d = dst[e];
    const int p = atomicAdd(&g_pos[d], 1);

    const float2* efp = reinterpret_cast<const float2*>(ef + (size_t)e * ED);
    const float2 f0 = efp[0], f1 = efp[1], f2 = efp[2];

    float4* rec = reinterpret_cast<float4*>(g_edges) + (size_t)p * 2;
    rec[0] = make_float4(__int_as_float(src[e]), f0.x, f0.y, f1.x);
    rec[1] = make_float4(f1.y, f2.x, f2.y, 0.f);
}

// ---------------------------------------------------------------------------
// Fused layer: warp-per-node CSR gather (no atomics) + update GEMM.
// Reads P[pin], writes P[pout] (double-buffered: no cross-block hazard).
// ---------------------------------------------------------------------------
__global__ void __launch_bounds__(256) layer_kernel(const float* __restrict__ Wg,
                                                    const float* __restrict__ Wu,
                                                    float* __restrict__ out,
                                                    int pin, int is_final)
{
    __shared__ float sWe[ED * HID];        // Wg rows 10..15
    __shared__ float sWu[2 * HID * HID];
    __shared__ float sWgh[HID * HID];      // Wg rows 0..9
    const int tid = threadIdx.x;
    if (tid < ED * HID) sWe[tid] = Wg[HID * HID + tid];
    if (tid < 2 * HID * HID) sWu[tid] = Wu[tid];
    if (tid < HID * HID) sWgh[tid] = Wg[tid];
    __syncthreads();

    const int warp = (blockIdx.x * blockDim.x + tid) >> 5;
    const int lane = tid & 31;
    if (warp >= NN) return;

    const float* __restrict__ Pin = g_P[pin];
    float* __restrict__ Pout = g_P[pin ^ 1];

    const int start = g_off[warp];
    const int end = g_off[warp + 1];

    float acc[HID];
#pragma unroll
    for (int j = 0; j < HID; j++) acc[j] = 0.f;

    for (int i = start + lane; i < end; i += 32) {
        const float4* rec = reinterpret_cast<const float4*>(g_edges) + (size_t)i * 2;
        const float4 r0 = rec[0];
        const float4 r1 = rec[1];
        const int s = __float_as_int(r0.x);
        const float efv[ED] = {r0.y, r0.z, r0.w, r1.x, r1.y, r1.z};

        const float* Pr = Pin + (size_t)s * PSTR;
        const float4 p0 = *reinterpret_cast<const float4*>(Pr);
        const float4 p1 = *reinterpret_cast<const float4*>(Pr + 4);
        const float2 p2 = *reinterpret_cast<const float2*>(Pr + 8);

        float m[HID] = {p0.x, p0.y, p0.z, p0.w, p1.x, p1.y, p1.z, p1.w, p2.x, p2.y};
#pragma unroll
        for (int k = 0; k < ED; k++)
#pragma unroll
            for (int j = 0; j < HID; j++) m[j] += efv[k] * sWe[k * HID + j];
#pragma unroll
        for (int j = 0; j < HID; j++) acc[j] += lrelu(m[j]);
    }

    // warp reduction: every lane ends with the full agg vector
#pragma unroll
    for (int off = 16; off; off >>= 1)
#pragma unroll
        for (int j = 0; j < HID; j++)
            acc[j] += __shfl_xor_sync(0xffffffffu, acc[j], off);

    // update GEMM: lane j (<10) computes output channel j
    const int j = (lane < HID) ? lane : 0;
    const float hk = (lane < HID) ? g_h[(size_t)warp * HID + lane] : 0.f;

    float o = 0.f;
#pragma unroll
    for (int k = 0; k < HID; k++) {
        const float hv = __shfl_sync(0xffffffffu, hk, k);
        o += hv * sWu[k * HID + j];
    }
#pragma unroll
    for (int k = 0; k < HID; k++)
        o += acc[k] * sWu[(HID + k) * HID + j];

    const float hn = lrelu(o);

    if (is_final) {
        if (lane < HID) out[(size_t)warp * HID + lane] = hn;
    } else {
        if (lane < HID) g_h[(size_t)warp * HID + lane] = hn;  // own-node only: safe
        float pn = 0.f;
#pragma unroll
        for (int k = 0; k < HID; k++) {
            const float hv = __shfl_sync(0xffffffffu, hn, k);
            pn += hv * sWgh[k * HID + j];
        }
        if (lane < HID) Pout[(size_t)warp * PSTR + lane] = pn;  // other buffer: safe
    }
}

// ---------------------------------------------------------------------------
extern "C" void kernel_launch(void* const* d_in, const int* in_sizes, int n_in,
                              void* d_out, int out_size)
{
    const float* vertex = (const float*)d_in[0];
    const float* ef     = (const float*)d_in[1];
    const int*   src    = (const int*)d_in[2];
    const int*   dst    = (const int*)d_in[3];
    const float* Wi     = (const float*)d_in[4];
    const float* Wg     = (const float*)d_in[5];
    const float* Wu     = (const float*)d_in[6];
    float* out = (float*)d_out;

    init_kernel<<<(NN + 127) / 128, 128>>>(vertex, Wi, Wg);

    // CSR build (graph static across layers -> amortized over both)
    zero_deg_kernel<<<(NN + 255) / 256, 256>>>();
    hist_kernel<<<(NE + 255) / 256, 256>>>(dst);
    scan1_kernel<<<NB1, 256>>>();
    scan2_kernel<<<1, 256>>>();
    scan3_kernel<<<NB1, 256>>>();
    permute_kernel<<<(NE + 255) / 256, 256>>>(ef, src, dst);

    const int lblocks = (NN * 32 + 255) / 256;  // one warp per node
    for (int depth = 0; depth < 2; depth++)
        layer_kernel<<<lblocks, 256>>>(Wg, Wu, out, depth, depth == 1);
}